// round 1
// baseline (speedup 1.0000x reference)
#include <cuda_runtime.h>
#include <math.h>

// Problem constants
#define NG   16          // NUM_GRIDS
#define NIX  32          // IN_X
#define NIZ  32          // IN_Z
#define NOUT 64          // OUT
#define NB   512         // BATCH
#define NC   17          // NUM_GRIDS + 1
#define IJ   (NIX * NIZ)         // 1024
#define JSTR (IJ * NOUT)         // 65536 floats: jj -> jj+1 step in P2
#define ISTR (NC * JSTR)         // ii -> ii+1 step in P2

// Repacked parameter tensor: P2[ii][jj][i*32+j][o]  (o contiguous)
// 17*17*1024*64 floats = 75.76 MB static device scratch (allowed).
__device__ float g_P2[NC * NC * IJ * NOUT];

// ---------------------------------------------------------------------------
// Repack: P[ii][jj][o][ij]  ->  P2[ii][jj][ij][o]
// 289 independent 64x1024 transposes, tiled 32x32 through smem.
// Reads coalesced along ij, writes coalesced along o.
// ---------------------------------------------------------------------------
__global__ __launch_bounds__(256) void repack_kernel(const float* __restrict__ P) {
    __shared__ float tile[32][33];
    const int cell = blockIdx.z;              // 0..288  (ii*17+jj)
    const int o0   = blockIdx.y << 5;         // 0 or 32
    const int ij0  = blockIdx.x << 5;         // 0..992
    const float* src = P     + cell * (NOUT * IJ);
    float*       dst = g_P2  + cell * (IJ * NOUT);
    const int tx = threadIdx.x;               // 32
    const int ty = threadIdx.y;               // 8
#pragma unroll
    for (int r = 0; r < 32; r += 8)
        tile[ty + r][tx] = src[(o0 + ty + r) * IJ + (ij0 + tx)];
    __syncthreads();
#pragma unroll
    for (int r = 0; r < 32; r += 8)
        dst[(ij0 + ty + r) * NOUT + (o0 + tx)] = tile[tx][ty + r];
}

// ---------------------------------------------------------------------------
// Gather: one block per batch. 256 threads = 16 o-quads (float4) x 16 ij-groups.
// Each thread accumulates 4 'o' outputs over 64 (i,j) pairs, 4 corners each.
// Corner loads are float4, half-warp-coalesced 256B lines from P2.
// ---------------------------------------------------------------------------
__global__ __launch_bounds__(256) void gather_kernel(
    const float* __restrict__ x,
    const float* __restrict__ z,
    const float* __restrict__ borders,
    const float* __restrict__ invlen,
    float* __restrict__ out)
{
    const int b   = blockIdx.x;
    const int tid = threadIdx.x;

    __shared__ int   s_ix[NIX];
    __shared__ int   s_iz[NIZ];
    __shared__ float s_dx[NIX];
    __shared__ float s_dz[NIZ];

    // Per-batch index/weight precompute (laplace cdf binning)
    if (tid < 64) {
        const float v = (tid < 32) ? x[tid * NB + b] : z[(tid - 32) * NB + b];
        const float e = expf(-fabsf(v));
        const float cdf = (v > 0.0f) ? (1.0f - 0.5f * e) : (0.5f * e);
        int idx = (int)(cdf * (float)NG);
        idx = max(0, min(NG - 1, idx));
        const float d = (v - borders[idx]) * invlen[idx];
        if (tid < 32) { s_ix[tid] = idx;      s_dx[tid] = d; }
        else          { s_iz[tid - 32] = idx; s_dz[tid - 32] = d; }
    }
    __syncthreads();

    const int ox = tid & 15;    // which float4 of the 64 'o' outputs
    const int yy = tid >> 4;    // ij-group 0..15

    float4 acc = make_float4(0.f, 0.f, 0.f, 0.f);

#pragma unroll 4
    for (int ij = yy; ij < IJ; ij += 16) {
        const int i = ij >> 5;
        const int j = ij & 31;
        const int   ix = s_ix[i];
        const int   iz = s_iz[j];
        const float dx = s_dx[i];
        const float dz = s_dz[j];
        const float ax = 1.0f - dx;
        const float az = 1.0f - dz;
        const float w00 = ax * az;
        const float w01 = ax * dz;
        const float w10 = dx * az;
        const float w11 = dx * dz;

        const int base = ((ix * NC + iz) * IJ + ij) * NOUT;   // < 2^31, 32-bit ok
        const float4* p = reinterpret_cast<const float4*>(g_P2 + base) + ox;

        const float4 p00 = p[0];
        const float4 p01 = p[JSTR / 4];
        const float4 p10 = p[ISTR / 4];
        const float4 p11 = p[(ISTR + JSTR) / 4];

        acc.x += w00 * p00.x + w01 * p01.x + w10 * p10.x + w11 * p11.x;
        acc.y += w00 * p00.y + w01 * p01.y + w10 * p10.y + w11 * p11.y;
        acc.z += w00 * p00.z + w01 * p01.z + w10 * p10.z + w11 * p11.z;
        acc.w += w00 * p00.w + w01 * p01.w + w10 * p10.w + w11 * p11.w;
    }

    // Reduce the 16 ij-groups
    __shared__ float4 s_red[16][17];   // pad to dodge bank conflicts
    s_red[yy][ox] = acc;
    __syncthreads();

    if (yy == 0) {
        float4 a = s_red[0][ox];
#pragma unroll
        for (int k = 1; k < 16; k++) {
            const float4 t = s_red[k][ox];
            a.x += t.x; a.y += t.y; a.z += t.z; a.w += t.w;
        }
        const int o = ox << 2;
        out[(o + 0) * NB + b] = a.x;
        out[(o + 1) * NB + b] = a.y;
        out[(o + 2) * NB + b] = a.z;
        out[(o + 3) * NB + b] = a.w;
    }
}

// ---------------------------------------------------------------------------
extern "C" void kernel_launch(void* const* d_in, const int* in_sizes, int n_in,
                              void* d_out, int out_size) {
    const float* x       = (const float*)d_in[0];  // (32, 512)
    const float* z       = (const float*)d_in[1];  // (32, 512)
    const float* P       = (const float*)d_in[2];  // (17,17,64,32,32)
    const float* borders = (const float*)d_in[3];  // (17,)
    const float* invlen  = (const float*)d_in[4];  // (16,)
    float* out = (float*)d_out;                    // (64, 512)

    (void)in_sizes; (void)n_in; (void)out_size;

    // Phase 1: repack P -> P2 (o contiguous)
    {
        dim3 grid(IJ / 32, NOUT / 32, NC * NC);    // (32, 2, 289)
        dim3 block(32, 8);
        repack_kernel<<<grid, block>>>(P);
    }

    // Phase 2: gather + accumulate
    {
        gather_kernel<<<NB, 256>>>(x, z, borders, invlen, out);
    }
}